// round 5
// baseline (speedup 1.0000x reference)
#include <cuda_runtime.h>
#include <cstdint>
#include <cstddef>

#define N_PTS 8192
#define DD    256
#define BATCH 8
#define S_MAX 2048

// Scratch (static device globals — allocation-free per harness rules)
__device__ int   g_idx[BATCH * S_MAX];          // FPS indices (prefix-shared across scales)
__device__ float g_h[28672 * 256];              // layer-1 / fusion-layer-1 outputs
__device__ float g_proc[28672 * 256];           // proc0 | proc1 | proc2 (rows 0,4096,12288)

// ---- packed f32x2 helpers (per-lane IEEE rn — bit-identical to scalar ops) ----
__device__ __forceinline__ unsigned long long pk2(float lo, float hi) {
    unsigned long long r;
    asm("mov.b64 %0, {%1, %2};" : "=l"(r) : "f"(lo), "f"(hi));
    return r;
}
__device__ __forceinline__ void upk2(unsigned long long v, float& lo, float& hi) {
    asm("mov.b64 {%0, %1}, %2;" : "=f"(lo), "=f"(hi) : "l"(v));
}
__device__ __forceinline__ unsigned long long add2(unsigned long long a, unsigned long long b) {
    unsigned long long r;
    asm("add.rn.f32x2 %0, %1, %2;" : "=l"(r) : "l"(a), "l"(b));
    return r;
}
__device__ __forceinline__ unsigned long long mul2(unsigned long long a, unsigned long long b) {
    unsigned long long r;
    asm("mul.rn.f32x2 %0, %1, %2;" : "=l"(r) : "l"(a), "l"(b));
    return r;
}
__device__ __forceinline__ uint32_t smem_u32(const void* ptr) {
    uint32_t addr;
    asm("{ .reg .u64 tmp; cvta.to.shared.u64 tmp, %1; cvt.u32.u64 %0, tmp; }"
        : "=r"(addr) : "l"(ptr));
    return addr;
}
__device__ __forceinline__ uint32_t mapa_u32(uint32_t local_addr, int rank) {
    uint32_t r;
    asm("mapa.shared::cluster.u32 %0, %1, %2;" : "=r"(r) : "r"(local_addr), "r"(rank));
    return r;
}

// ---------------------------------------------------------------------------
// FPS: one 4-CTA CLUSTER per batch (32 CTAs total), 1024 threads/CTA,
// 2 points/thread (one f32x2 pair). Per-CTA winner is reduced exactly as
// before (REDUX.MAX on f32 bits + ballot/ffs: lane->warp order == index
// order). Each CTA's winner lies in its own point range, so the sender ships
// (val, idx, x, y, z) to all 4 CTAs' DSMEM mailboxes and release-arrives on
// each CTA's mbarrier; all threads acquire-wait locally and reduce the 4
// records with exact (max val, min idx) tie-break. Double-buffered by step
// parity: barrier/mailbox[s&1]; the step s+1 wait orders step-s reads before
// step s+2 overwrites. Distance arithmetic identical to prior rounds (rn,
// ((dx*dx+dy*dy)+dz*dz)) => bit-identical index sequence.
// ---------------------------------------------------------------------------
__global__ void __launch_bounds__(1024, 1) __cluster_dims__(4, 1, 1)
fps_kernel(const float* __restrict__ xyz, int* __restrict__ outIdx)
{
    const int cta  = blockIdx.x;
    const int b    = cta >> 2;
    const int rank = cta & 3;
    const float* p = xyz + (size_t)b * N_PTS * 3;
    const int t = threadIdx.x;
    const int lane = t & 31, wid = t >> 5;

    const int l0 = t * 2;             // local point ids (l0, l0+1)
    const int g0 = rank * 2048 + l0;  // global point ids

    __shared__ float sx[2048], sy[2048], sz[2048];     // own-range coords
    __shared__ unsigned s_val[2][32];
    __shared__ int      s_idx[2][32];
    __shared__ alignas(16) unsigned long long s_mbar[2];
    __shared__ alignas(16) unsigned long long s_mbox[2][4][3];  // [buf][srcRank][w0,w1,w2]

    // load own 2 points (registers + smem copy for winner-coord lookup)
    const float x0 = p[g0 * 3 + 0], y0 = p[g0 * 3 + 1], z0 = p[g0 * 3 + 2];
    const float x1 = p[g0 * 3 + 3], y1 = p[g0 * 3 + 4], z1 = p[g0 * 3 + 5];
    sx[l0] = x0; sy[l0] = y0; sz[l0] = z0;
    sx[l0 + 1] = x1; sy[l0 + 1] = y1; sz[l0 + 1] = z1;
    const unsigned long long px2 = pk2(x0, x1), py2 = pk2(y0, y1), pz2 = pk2(z0, z1);
    float dist0 = 1e10f, dist1 = 1e10f;

    const uint32_t mbar_a0 = smem_u32(&s_mbar[0]);
    const uint32_t mbar_a1 = smem_u32(&s_mbar[1]);
    if (t == 0) {
        asm volatile("mbarrier.init.shared.b64 [%0], %1;" :: "r"(mbar_a0), "r"(4u) : "memory");
        asm volatile("mbarrier.init.shared.b64 [%0], %1;" :: "r"(mbar_a1), "r"(4u) : "memory");
    }
    __syncthreads();
    asm volatile("barrier.cluster.arrive.aligned;" ::: "memory");
    asm volatile("barrier.cluster.wait.aligned;" ::: "memory");

    float qx = p[0], qy = p[1], qz = p[2];
    if (rank == 0 && t == 0) outIdx[b * S_MAX + 0] = 0;
    int ph0 = 0, ph1 = 0;

    for (int step = 1; step < S_MAX; step++) {
        const int buf = step & 1;

        // ---- distance update (bit-exact rn order) ----
        const unsigned long long nqx = pk2(-qx, -qx);
        const unsigned long long nqy = pk2(-qy, -qy);
        const unsigned long long nqz = pk2(-qz, -qz);
        unsigned long long dx = add2(px2, nqx);
        unsigned long long dy = add2(py2, nqy);
        unsigned long long dz = add2(pz2, nqz);
        unsigned long long s  = add2(mul2(dx, dx), mul2(dy, dy));
        unsigned long long d2 = add2(s, mul2(dz, dz));
        float d0, d1;
        upk2(d2, d0, d1);
        dist0 = fminf(dist0, d0);
        dist1 = fminf(dist1, d1);
        const float best = fmaxf(dist0, dist1);

        // ---- warp stage: REDUX.MAX on f32 bits + first-index recovery ----
        const unsigned bestbits = __float_as_uint(best);
        const unsigned wmax = __reduce_max_sync(0xFFFFFFFFu, bestbits);
        const unsigned bal  = __ballot_sync(0xFFFFFFFFu, bestbits == wmax);
        const int srcl = __ffs(bal) - 1;
        const int myi  = (__float_as_uint(dist0) == wmax) ? g0 : (g0 + 1);
        const int widx_w = __shfl_sync(0xFFFFFFFFu, myi, srcl);

        if (lane == 0) { s_val[buf][wid] = wmax; s_idx[buf][wid] = widx_w; }
        __syncthreads();

        // ---- block stage (all warps redundantly) ----
        const unsigned v = s_val[buf][lane];
        const unsigned cmax = __reduce_max_sync(0xFFFFFFFFu, v);
        const unsigned bal2 = __ballot_sync(0xFFFFFFFFu, v == cmax);
        const int ws = __ffs(bal2) - 1;
        const int cidx = s_idx[buf][ws];

        // ---- cluster exchange: sender ships (val,idx,x,y,z) to all 4 CTAs ----
        if (t == 0) {
            const int loc = cidx - rank * 2048;   // CTA winner is in own range
            const float cx = sx[loc], cy = sy[loc], cz = sz[loc];
            const unsigned long long w0 =
                ((unsigned long long)cmax << 32) | (unsigned)cidx;
            const unsigned long long w1 =
                ((unsigned long long)__float_as_uint(cy) << 32) | __float_as_uint(cx);
            const unsigned long long w2 = (unsigned long long)__float_as_uint(cz);
            const uint32_t mybox = smem_u32(&s_mbox[buf][rank][0]);
            const uint32_t mybar = (buf ? mbar_a1 : mbar_a0);
#pragma unroll
            for (int r = 0; r < 4; r++) {
                const uint32_t box = mapa_u32(mybox, r);
                asm volatile("st.shared::cluster.u64 [%0], %1;" :: "r"(box),      "l"(w0) : "memory");
                asm volatile("st.shared::cluster.u64 [%0], %1;" :: "r"(box + 8),  "l"(w1) : "memory");
                asm volatile("st.shared::cluster.u64 [%0], %1;" :: "r"(box + 16), "l"(w2) : "memory");
                const uint32_t bar = mapa_u32(mybar, r);
                asm volatile("mbarrier.arrive.release.cluster.shared::cluster.b64 _, [%0];"
                             :: "r"(bar) : "memory");
            }
        }

        // ---- wait (acquire, cluster scope) on local barrier; reduce 4 ----
        {
            const uint32_t bar = (buf ? mbar_a1 : mbar_a0);
            const int par = (buf ? ph1 : ph0);
            unsigned done;
            asm volatile(
                "{\n\t.reg .pred p;\n\t"
                "mbarrier.try_wait.parity.acquire.cluster.shared::cta.b64 p, [%1], %2;\n\t"
                "selp.b32 %0, 1, 0, p;\n\t}"
                : "=r"(done) : "r"(bar), "r"(par) : "memory");
            while (!done) {
                asm volatile(
                    "{\n\t.reg .pred p;\n\t"
                    "mbarrier.try_wait.parity.acquire.cluster.shared::cta.b64 p, [%1], %2;\n\t"
                    "selp.b32 %0, 1, 0, p;\n\t}"
                    : "=r"(done) : "r"(bar), "r"(par) : "memory");
            }
            if (buf) ph1 ^= 1; else ph0 ^= 1;
        }

        unsigned bv = 0; int bi = 0x7FFFFFFF;
        unsigned long long bw1 = 0, bw2 = 0;
#pragma unroll
        for (int r = 0; r < 4; r++) {
            const unsigned long long w0 = s_mbox[buf][r][0];
            const unsigned vv = (unsigned)(w0 >> 32);
            const int ii = (int)(unsigned)w0;
            if (vv > bv || (vv == bv && ii < bi)) {
                bv = vv; bi = ii;
                bw1 = s_mbox[buf][r][1];
                bw2 = s_mbox[buf][r][2];
            }
        }
        qx = __uint_as_float((unsigned)bw1);
        qy = __uint_as_float((unsigned)(bw1 >> 32));
        qz = __uint_as_float((unsigned)bw2);
        if (rank == 0 && t == 0) outIdx[b * S_MAX + step] = bi;
    }

    asm volatile("barrier.cluster.arrive.aligned;" ::: "memory");
    asm volatile("barrier.cluster.wait.aligned;" ::: "memory");
}

// ---------------------------------------------------------------------------
// Fused fp32 GEMM: C[M,256] = A[M,K] @ B[K,256] (+bias) (+LayerNorm+ReLU)
//   AMODE 0: MULTI-SCALE layer-1: block ranges cover all 3 scales in ONE grid;
//            A rows gathered via FPS idx from features [B,8192,256]
//   AMODE 1: A rows read directly (A + r*256)
//   AMODE 2: A rows are the virtual concat [proc0 | proc1 | proc2] (K=768)
//   AMODE 3: MULTI-SCALE layer-2: direct rows at per-scale offsets
//   EMODE 0: +bias, store
//   EMODE 1: +bias, LayerNorm(gamma,beta), ReLU, store
//   EMODE 2: +bias, store 4 tiled copies (n = m + k*2048) into [B,8192,256]
// Tile: BM=32, BN=256, BK=16, 256 threads, 4x8 microtile, double-buffered smem.
// Multi-scale block map (32-row blocks): [0,128)->s=512 rowoff=0,
//   [128,384)->s=1024 rowoff=4096, [384,896)->s=2048 rowoff=12288.
// ---------------------------------------------------------------------------
template <int AMODE, int EMODE>
__global__ void __launch_bounds__(256, 3)
gemm_fused(const float* __restrict__ A, const float* __restrict__ Bm,
           const float* __restrict__ bias, const float* __restrict__ gamma,
           const float* __restrict__ beta, float* __restrict__ C,
           int K, const int* __restrict__ idx)
{
    __shared__ float As[2][32][16];
    __shared__ float Bs[2][16][256];

    const int tid  = threadIdx.x;
    const int lane = tid & 31, warp = tid >> 5;

    int rowblock, sc = 0, rowoff = 0, sloc = 0;
    if (AMODE == 0 || AMODE == 3) {
        const int blk = blockIdx.x;
        if (blk < 128)      { sc = 0; rowblock = blk * 32;         sloc = 512;  rowoff = 0; }
        else if (blk < 384) { sc = 1; rowblock = (blk - 128) * 32; sloc = 1024; rowoff = 4096; }
        else                { sc = 2; rowblock = (blk - 384) * 32; sloc = 2048; rowoff = 12288; }
    } else {
        rowblock = blockIdx.x * 32;
    }
    const float* Bmp   = Bm + (size_t)sc * 65536;
    const float* biasp = bias + sc * 256;

    // ---- A-load mapping (threads 0..127 load one float4 per k-tile) ----
    const int arow = tid >> 2;            // 0..63 (only <32 used when tid<128)
    const int akq  = (tid & 3) << 2;      // {0,4,8,12}
    const int r    = rowblock + (arow & 31);
    const float* aptr0 = A;
    const float* aptr1 = A;
    const float* aptr2 = A;
    if (AMODE == 0) {
        int bb = r / sloc, j = r - bb * sloc;
        int src = idx[bb * 2048 + j];
        aptr0 = A + ((size_t)bb * 8192 + src) * 256;
    } else if (AMODE == 1) {
        aptr0 = A + (size_t)r * 256;
    } else if (AMODE == 3) {
        aptr0 = A + (size_t)(rowoff + r) * 256;
    } else {
        int bb = r >> 11, m = r & 2047;
        aptr0 = A +            ((size_t)bb * 512  + (m & 511))  * 256;
        aptr1 = A + 1048576 +  ((size_t)bb * 1024 + (m & 1023)) * 256;
        aptr2 = A + 3145728 +  ((size_t)bb * 2048 + m)          * 256;
    }
    const bool aload = (tid < 128);

    // ---- B-load mapping (4 float4 per thread per k-tile) ----
    const int brow = tid >> 6;            // 0..3
    const int bcol = (tid & 63) << 2;     // 0..252

    float acc[4][8];
#pragma unroll
    for (int i = 0; i < 4; i++)
#pragma unroll
        for (int j = 0; j < 8; j++) acc[i][j] = 0.f;

    const int ktiles = K >> 4;
    float4 ra;
    float4 rb[4];

    // prologue: load tile 0
    if (aload) ra = *reinterpret_cast<const float4*>(aptr0 + akq);
#pragma unroll
    for (int i = 0; i < 4; i++)
        rb[i] = *reinterpret_cast<const float4*>(Bmp + (size_t)(brow + 4 * i) * 256 + bcol);
    if (aload) *reinterpret_cast<float4*>(&As[0][arow][akq]) = ra;
#pragma unroll
    for (int i = 0; i < 4; i++)
        *reinterpret_cast<float4*>(&Bs[0][brow + 4 * i][bcol]) = rb[i];
    __syncthreads();

    for (int kt = 0; kt < ktiles; kt++) {
        const int cur = kt & 1;
        if (kt + 1 < ktiles) {
            const int k0 = (kt + 1) << 4;
            if (aload) {
                if (AMODE == 2) {
                    int seg = k0 >> 8;
                    int kk  = (k0 & 255) + akq;
                    const float* bp = (seg == 0) ? aptr0 : ((seg == 1) ? aptr1 : aptr2);
                    ra = *reinterpret_cast<const float4*>(bp + kk);
                } else {
                    ra = *reinterpret_cast<const float4*>(aptr0 + k0 + akq);
                }
            }
#pragma unroll
            for (int i = 0; i < 4; i++)
                rb[i] = *reinterpret_cast<const float4*>(Bmp + (size_t)(k0 + brow + 4 * i) * 256 + bcol);
        }
#pragma unroll
        for (int kk = 0; kk < 16; kk++) {
            float a[4];
#pragma unroll
            for (int ii = 0; ii < 4; ii++) a[ii] = As[cur][warp * 4 + ii][kk];
            float4 b0 = *reinterpret_cast<const float4*>(&Bs[cur][kk][lane * 4]);
            float4 b1 = *reinterpret_cast<const float4*>(&Bs[cur][kk][128 + lane * 4]);
            float bv[8] = {b0.x, b0.y, b0.z, b0.w, b1.x, b1.y, b1.z, b1.w};
#pragma unroll
            for (int ii = 0; ii < 4; ii++)
#pragma unroll
                for (int jj = 0; jj < 8; jj++)
                    acc[ii][jj] = fmaf(a[ii], bv[jj], acc[ii][jj]);
        }
        if (kt + 1 < ktiles) {
            const int nb = cur ^ 1;
            if (aload) *reinterpret_cast<float4*>(&As[nb][arow][akq]) = ra;
#pragma unroll
            for (int i = 0; i < 4; i++)
                *reinterpret_cast<float4*>(&Bs[nb][brow + 4 * i][bcol]) = rb[i];
        }
        __syncthreads();
    }

    // ---- epilogue ----
    const int c0 = lane * 4, c1 = 128 + lane * 4;
    {
        float4 t0 = *reinterpret_cast<const float4*>(biasp + c0);
        float4 t1 = *reinterpret_cast<const float4*>(biasp + c1);
        float bsv[8] = {t0.x, t0.y, t0.z, t0.w, t1.x, t1.y, t1.z, t1.w};
#pragma unroll
        for (int ii = 0; ii < 4; ii++)
#pragma unroll
            for (int jj = 0; jj < 8; jj++) acc[ii][jj] += bsv[jj];
    }

    float gv[8], ev[8];
    if (EMODE == 1) {
        const float* gp = gamma + sc * 256;
        const float* bp = beta + sc * 256;
        float4 t0 = *reinterpret_cast<const float4*>(gp + c0);
        float4 t1 = *reinterpret_cast<const float4*>(gp + c1);
        gv[0]=t0.x; gv[1]=t0.y; gv[2]=t0.z; gv[3]=t0.w;
        gv[4]=t1.x; gv[5]=t1.y; gv[6]=t1.z; gv[7]=t1.w;
        float4 u0 = *reinterpret_cast<const float4*>(bp + c0);
        float4 u1 = *reinterpret_cast<const float4*>(bp + c1);
        ev[0]=u0.x; ev[1]=u0.y; ev[2]=u0.z; ev[3]=u0.w;
        ev[4]=u1.x; ev[5]=u1.y; ev[6]=u1.z; ev[7]=u1.w;
    }

#pragma unroll
    for (int ii = 0; ii < 4; ii++) {
        const int row = rowoff + rowblock + warp * 4 + ii;
        float o8[8];
        if (EMODE == 1) {
            float sum = 0.f;
#pragma unroll
            for (int jj = 0; jj < 8; jj++) sum += acc[ii][jj];
#pragma unroll
            for (int o = 16; o > 0; o >>= 1) sum += __shfl_xor_sync(0xFFFFFFFFu, sum, o);
            const float mu = sum * (1.0f / 256.0f);
            float sq = 0.f;
#pragma unroll
            for (int jj = 0; jj < 8; jj++) {
                float dd = acc[ii][jj] - mu;
                sq += dd * dd;
            }
#pragma unroll
            for (int o = 16; o > 0; o >>= 1) sq += __shfl_xor_sync(0xFFFFFFFFu, sq, o);
            const float sc2 = rsqrtf(sq * (1.0f / 256.0f) + 1e-5f);
#pragma unroll
            for (int jj = 0; jj < 8; jj++) {
                float v = fmaf((acc[ii][jj] - mu) * sc2, gv[jj], ev[jj]);
                o8[jj] = fmaxf(v, 0.f);
            }
        } else {
#pragma unroll
            for (int jj = 0; jj < 8; jj++) o8[jj] = acc[ii][jj];
        }
        float4 s0 = make_float4(o8[0], o8[1], o8[2], o8[3]);
        float4 s1 = make_float4(o8[4], o8[5], o8[6], o8[7]);
        if (EMODE == 2) {
            const int bb2 = row >> 11, m = row & 2047;
            const size_t base0 = ((size_t)bb2 * 8192 + m) * 256;
#pragma unroll
            for (int rep = 0; rep < 4; rep++) {
                *reinterpret_cast<float4*>(C + base0 + (size_t)rep * 524288 + c0) = s0;
                *reinterpret_cast<float4*>(C + base0 + (size_t)rep * 524288 + c1) = s1;
            }
        } else {
            *reinterpret_cast<float4*>(C + (size_t)row * 256 + c0) = s0;
            *reinterpret_cast<float4*>(C + (size_t)row * 256 + c1) = s1;
        }
    }
}

// ---------------------------------------------------------------------------
extern "C" void kernel_launch(void* const* d_in, const int* in_sizes, int n_in,
                              void* d_out, int out_size)
{
    const float* features = (const float*)d_in[0];
    const float* xyz      = (const float*)d_in[1];
    const float* w1  = (const float*)d_in[2];
    const float* b1  = (const float*)d_in[3];
    const float* g1  = (const float*)d_in[4];
    const float* be1 = (const float*)d_in[5];
    const float* w2  = (const float*)d_in[6];
    const float* b2  = (const float*)d_in[7];
    const float* fw1 = (const float*)d_in[8];
    const float* fb1 = (const float*)d_in[9];
    const float* fg  = (const float*)d_in[10];
    const float* fbe = (const float*)d_in[11];
    const float* fw2 = (const float*)d_in[12];
    const float* fb2 = (const float*)d_in[13];
    float* out = (float*)d_out;

    int*   idxp;
    float* hp;
    float* procp;
    cudaGetSymbolAddress((void**)&idxp, g_idx);
    cudaGetSymbolAddress((void**)&hp, g_h);
    cudaGetSymbolAddress((void**)&procp, g_proc);

    // 1) One FPS run per batch (4-CTA cluster per batch); smaller scales are prefixes.
    fps_kernel<<<BATCH * 4, 1024>>>(xyz, idxp);

    // 2) All 3 per-scale MLPs, each layer as ONE 896-CTA launch.
    gemm_fused<0, 1><<<896, 256>>>(features, w1, b1, g1, be1, hp, 256, idxp);
    gemm_fused<3, 0><<<896, 256>>>(hp, w2, b2, nullptr, nullptr, procp, 256, nullptr);

    // 3) Fusion MLP on only B*2048 distinct rows (output depends on n mod 2048),
    //    final GEMM epilogue writes each row 4x to rebuild [B, 8192, D].
    gemm_fused<2, 1><<<512, 256>>>(procp, fw1, fb1, fg, fbe, hp, 768, nullptr);
    gemm_fused<1, 2><<<512, 256>>>(hp, fw2, fb2, nullptr, nullptr, out, 256, nullptr);
}

// round 10
// speedup vs baseline: 2.0886x; 2.0886x over previous
#include <cuda_runtime.h>
#include <cuda_bf16.h>
#include <cstdint>
#include <cstddef>

typedef unsigned int u32;
typedef unsigned long long u64;

#define BATCH 8
#define N_PTS 8192
#define S_MAX 2048

// ---------------- device scratch (allocation-free) ----------------
__device__ int g_idx[BATCH * S_MAX];
__device__ u32 g_featP[BATCH * N_PTS * 256];   // features split-packed (lo<<16|hi)
__device__ u32 g_h1[28672 * 256];              // L1 out packed
__device__ u32 g_procP[16384 * 768];           // fusion input packed (concat, dup)
__device__ u32 g_h2[16384 * 256];              // F1 out packed
__device__ u32 g_w1t[3 * 256 * 256];           // transposed split weights [N,K]
__device__ u32 g_w2t[3 * 256 * 256];
__device__ u32 g_fw1t[256 * 768];
__device__ u32 g_fw2t[256 * 256];

// ---- packed f32x2 helpers (per-lane IEEE rn — bit-identical to scalar) ----
__device__ __forceinline__ u64 pk2(float lo, float hi) {
    u64 r; asm("mov.b64 %0, {%1, %2};" : "=l"(r) : "f"(lo), "f"(hi)); return r;
}
__device__ __forceinline__ void upk2(u64 v, float& lo, float& hi) {
    asm("mov.b64 {%0, %1}, %2;" : "=f"(lo), "=f"(hi) : "l"(v));
}
__device__ __forceinline__ u64 add2(u64 a, u64 b) {
    u64 r; asm("add.rn.f32x2 %0, %1, %2;" : "=l"(r) : "l"(a), "l"(b)); return r;
}
__device__ __forceinline__ u64 mul2(u64 a, u64 b) {
    u64 r; asm("mul.rn.f32x2 %0, %1, %2;" : "=l"(r) : "l"(a), "l"(b)); return r;
}

// ---------------------------------------------------------------------------
// FPS (R4, known exact): 1 CTA/batch, 1024 thr, 8 pts/thr, REDUX argmax.
// ---------------------------------------------------------------------------
__global__ void __launch_bounds__(1024, 1)
fps_kernel(const float* __restrict__ xyz, int* __restrict__ outIdx)
{
    const int b = blockIdx.x;
    const float* p = xyz + (size_t)b * N_PTS * 3;
    const int t = threadIdx.x;
    const int lane = t & 31, wid = t >> 5;
    const int base = t * 8;

    u64 px2[4], py2[4], pz2[4];
    float dist[8];
#pragma unroll
    for (int j = 0; j < 4; j++) {
        const int k0 = base + 2 * j, k1 = k0 + 1;
        px2[j] = pk2(p[k0 * 3 + 0], p[k1 * 3 + 0]);
        py2[j] = pk2(p[k0 * 3 + 1], p[k1 * 3 + 1]);
        pz2[j] = pk2(p[k0 * 3 + 2], p[k1 * 3 + 2]);
    }
#pragma unroll
    for (int k = 0; k < 8; k++) dist[k] = 1e10f;

    __shared__ unsigned s_val[2][32];
    __shared__ int      s_idx[2][32];

    float qx = p[0], qy = p[1], qz = p[2];
    if (t == 0) outIdx[b * S_MAX + 0] = 0;

    for (int step = 1; step < S_MAX; step++) {
        const u64 nqx = pk2(-qx, -qx);
        const u64 nqy = pk2(-qy, -qy);
        const u64 nqz = pk2(-qz, -qz);

        float best = -1.0f;
        int bidx = 0;
#pragma unroll
        for (int j = 0; j < 4; j++) {
            u64 dx = add2(px2[j], nqx);
            u64 dy = add2(py2[j], nqy);
            u64 dz = add2(pz2[j], nqz);
            u64 s  = add2(mul2(dx, dx), mul2(dy, dy));
            u64 d2 = add2(s, mul2(dz, dz));
            float d0, d1;
            upk2(d2, d0, d1);
            float nd0 = fminf(dist[2 * j + 0], d0);
            float nd1 = fminf(dist[2 * j + 1], d1);
            dist[2 * j + 0] = nd0;
            dist[2 * j + 1] = nd1;
            if (nd0 > best) { best = nd0; bidx = base + 2 * j + 0; }
            if (nd1 > best) { best = nd1; bidx = base + 2 * j + 1; }
        }
        const unsigned bestbits = __float_as_uint(best);
        const unsigned wmax = __reduce_max_sync(0xFFFFFFFFu, bestbits);
        const unsigned bal  = __ballot_sync(0xFFFFFFFFu, bestbits == wmax);
        const int srcl = __ffs(bal) - 1;
        const int widx_w = __shfl_sync(0xFFFFFFFFu, bidx, srcl);

        const int buf = step & 1;
        if (lane == 0) { s_val[buf][wid] = wmax; s_idx[buf][wid] = widx_w; }
        __syncthreads();
        const unsigned v = s_val[buf][lane];
        const unsigned bmax = __reduce_max_sync(0xFFFFFFFFu, v);
        const unsigned bal2 = __ballot_sync(0xFFFFFFFFu, v == bmax);
        const int wsrc = __ffs(bal2) - 1;
        const int widx = s_idx[buf][wsrc];

        if (t == 0) outIdx[b * S_MAX + step] = widx;
        qx = p[widx * 3 + 0];
        qy = p[widx * 3 + 1];
        qz = p[widx * 3 + 2];
    }
}

// ---------------------------------------------------------------------------
// Conversion: f32 -> packed (bf16_lo << 16 | bf16_hi)
// ---------------------------------------------------------------------------
__device__ __forceinline__ u32 split_pack_val(float v) {
    __nv_bfloat16 h = __float2bfloat16(v);
    float r = v - __bfloat162float(h);
    __nv_bfloat16 l = __float2bfloat16(r);
    return ((u32)__bfloat16_as_ushort(l) << 16) | (u32)__bfloat16_as_ushort(h);
}
__global__ void split_pack(const float* __restrict__ src, u32* __restrict__ dst, int n) {
    int i = blockIdx.x * blockDim.x + threadIdx.x;
    if (i < n) dst[i] = split_pack_val(src[i]);
}
// w[K,N] f32 -> wt[N,K] packed
__global__ void tsplit(const float* __restrict__ src, u32* __restrict__ dst, int K, int N) {
    int i = blockIdx.x * blockDim.x + threadIdx.x;
    if (i >= N * K) return;
    int n = i / K, k = i - n * K;
    dst[i] = split_pack_val(src[k * N + n]);
}

// ---------------------------------------------------------------------------
// HMMA (mma.sync m16n8k16 bf16) GEMM: C[64rows,256] = A @ B^T, B stored [256,K].
// 3 passes fused in k-loop: Ah*Bh + Ah*Bl + Al*Bh, fp32 register accumulators.
//   AMODE 0: A rows gathered via FPS idx (L1)   AMODE 1: direct rows r*Ktot
//   AMODE 3: direct rows at (hoff+r)*256 (L2)
//   EMODE 1: +bias, LayerNorm, ReLU -> packed   EMODE 3: +bias -> packed concat dup
//   EMODE 2: +bias -> f32, 4 tiled copies into [B,8192,256]
// smem (dynamic): As_hi/lo [64][20]u32, Bs_hi/lo [256][20]u32, ps[2][64]float2,
//                 rowoff[64]  => 52608 B
// ---------------------------------------------------------------------------
#define TCG_SMEM 52608

__device__ __forceinline__ void mma16816(float* c, const u32* a, u32 b0, u32 b1) {
    asm volatile(
        "mma.sync.aligned.m16n8k16.row.col.f32.bf16.bf16.f32 "
        "{%0,%1,%2,%3}, {%4,%5,%6,%7}, {%8,%9}, {%0,%1,%2,%3};"
        : "+f"(c[0]), "+f"(c[1]), "+f"(c[2]), "+f"(c[3])
        : "r"(a[0]), "r"(a[1]), "r"(a[2]), "r"(a[3]), "r"(b0), "r"(b1));
}

template <int AMODE, int EMODE>
__global__ void __launch_bounds__(256, 2)
tc_gemm(const u32* __restrict__ Apk, const u32* __restrict__ Bpk,
        const float* __restrict__ bias, const float* __restrict__ gamma,
        const float* __restrict__ beta, void* __restrict__ Cout,
        int Ktot, const int* __restrict__ idx)
{
    extern __shared__ char smem[];
    u32*    As_hi = (u32*)smem;                    // 64*20
    u32*    As_lo = As_hi + 64 * 20;
    u32*    Bs_hi = As_lo + 64 * 20;               // 256*20
    u32*    Bs_lo = Bs_hi + 256 * 20;
    float2* s_ps  = (float2*)(Bs_lo + 256 * 20);   // [2][64]
    u32*    s_ro  = (u32*)(s_ps + 128);            // [64]

    const int tid  = threadIdx.x;
    const int w    = tid >> 5, lane = tid & 31;
    const int g    = lane >> 2, lq = lane & 3;
    const int mrow = (w & 3) * 16;
    const int half = w >> 2;
    const int ncol0 = half * 128;

    // tile / scale mapping (64-row blocks)
    int rowblock, sc = 0, hoff = 0, ss = 11;
    if (AMODE == 0 || AMODE == 3) {
        const int blk = blockIdx.x;
        if (blk < 64)       { sc = 0; rowblock = blk * 64;         ss = 9;  hoff = 0; }
        else if (blk < 192) { sc = 1; rowblock = (blk - 64) * 64;  ss = 10; hoff = 4096; }
        else                { sc = 2; rowblock = (blk - 192) * 64; ss = 11; hoff = 12288; }
    } else {
        rowblock = blockIdx.x * 64;
    }
    const u32*   Bp    = Bpk + (size_t)sc * 256 * Ktot;
    const float* biasp = bias + sc * 256;

    if (tid < 64) {
        const int r = rowblock + tid;
        u32 off;
        if (AMODE == 0) {
            const int bb = r >> ss, j = r & ((1 << ss) - 1);
            off = (u32)((bb * 8192 + idx[bb * 2048 + j]) * 256);
        } else if (AMODE == 3) {
            off = (u32)((hoff + r) * 256);
        } else {
            off = (u32)(r * Ktot);
        }
        s_ro[tid] = off;
    }

    float acc[16][4];
#pragma unroll
    for (int t = 0; t < 16; t++)
#pragma unroll
        for (int j = 0; j < 4; j++) acc[t][j] = 0.f;

    const int nch = Ktot >> 5;
    for (int c = 0; c < nch; c++) {
        const int kc = c << 5;
        __syncthreads();     // protect prior iteration's reads (no-op on entry)
        // ---- stage A: 64x32 packed -> hi/lo pair tiles ----
#pragma unroll
        for (int i = 0; i < 2; i++) {
            const int id2 = tid + (i << 8);
            const int row = id2 >> 3, kq = (id2 & 7) << 2;
            const uint4 p = *(const uint4*)(Apk + s_ro[row] + kc + kq);
            const u32 h0 = (p.x & 0xFFFFu) | (p.y << 16);
            const u32 l0 = (p.x >> 16) | (p.y & 0xFFFF0000u);
            const u32 h1 = (p.z & 0xFFFFu) | (p.w << 16);
            const u32 l1 = (p.z >> 16) | (p.w & 0xFFFF0000u);
            const int bo = row * 20 + (kq >> 1);
            *(uint2*)(As_hi + bo) = make_uint2(h0, h1);
            *(uint2*)(As_lo + bo) = make_uint2(l0, l1);
        }
        // ---- stage B: 256x32 packed -> hi/lo pair tiles ----
#pragma unroll
        for (int i = 0; i < 8; i++) {
            const int id2 = tid + (i << 8);
            const int row = id2 >> 3, kq = (id2 & 7) << 2;
            const uint4 p = *(const uint4*)(Bp + (size_t)row * Ktot + kc + kq);
            const u32 h0 = (p.x & 0xFFFFu) | (p.y << 16);
            const u32 l0 = (p.x >> 16) | (p.y & 0xFFFF0000u);
            const u32 h1 = (p.z & 0xFFFFu) | (p.w << 16);
            const u32 l1 = (p.z >> 16) | (p.w & 0xFFFF0000u);
            const int bo = row * 20 + (kq >> 1);
            *(uint2*)(Bs_hi + bo) = make_uint2(h0, h1);
            *(uint2*)(Bs_lo + bo) = make_uint2(l0, l1);
        }
        __syncthreads();
        // ---- compute: 2 x k16 ----
#pragma unroll
        for (int ks = 0; ks < 2; ks++) {
            const int kb = ks << 3;           // u32 column base (0 or 8)
            const int r0 = mrow + g;
            u32 a_h[4], a_l[4];
            a_h[0] = As_hi[r0 * 20 + kb + lq];
            a_h[1] = As_hi[(r0 + 8) * 20 + kb + lq];
            a_h[2] = As_hi[r0 * 20 + kb + 4 + lq];
            a_h[3] = As_hi[(r0 + 8) * 20 + kb + 4 + lq];
            a_l[0] = As_lo[r0 * 20 + kb + lq];
            a_l[1] = As_lo[(r0 + 8) * 20 + kb + lq];
            a_l[2] = As_lo[r0 * 20 + kb + 4 + lq];
            a_l[3] = As_lo[(r0 + 8) * 20 + kb + 4 + lq];
#pragma unroll
            for (int t = 0; t < 16; t++) {
                const int nr = ncol0 + t * 8 + g;
                const u32 bh0 = Bs_hi[nr * 20 + kb + lq];
                const u32 bh1 = Bs_hi[nr * 20 + kb + 4 + lq];
                const u32 bl0 = Bs_lo[nr * 20 + kb + lq];
                const u32 bl1 = Bs_lo[nr * 20 + kb + 4 + lq];
                mma16816(acc[t], a_h, bh0, bh1);
                mma16816(acc[t], a_h, bl0, bl1);
                mma16816(acc[t], a_l, bh0, bh1);
            }
        }
    }

    // ---- epilogue ----
    // bias add (cols shared by both row-halves of each accum tile)
    float2 bv[16];
#pragma unroll
    for (int t = 0; t < 16; t++) {
        bv[t] = *(const float2*)(biasp + ncol0 + t * 8 + lq * 2);
        acc[t][0] += bv[t].x; acc[t][1] += bv[t].y;
        acc[t][2] += bv[t].x; acc[t][3] += bv[t].y;
    }

    const int rAl = mrow + g, rBl = rAl + 8;     // local rows 0..63
    float muA = 0.f, rsA = 1.f, muB = 0.f, rsB = 1.f;
    if (EMODE == 1) {
        float sA = 0.f, qA = 0.f, sB = 0.f, qB = 0.f;
#pragma unroll
        for (int t = 0; t < 16; t++) {
            sA += acc[t][0] + acc[t][1];
            qA += acc[t][0] * acc[t][0] + acc[t][1] * acc[t][1];
            sB += acc[t][2] + acc[t][3];
            qB += acc[t][2] * acc[t][2] + acc[t][3] * acc[t][3];
        }
#pragma unroll
        for (int o = 1; o <= 2; o <<= 1) {
            sA += __shfl_xor_sync(0xFFFFFFFFu, sA, o);
            qA += __shfl_xor_sync(0xFFFFFFFFu, qA, o);
            sB += __shfl_xor_sync(0xFFFFFFFFu, sB, o);
            qB += __shfl_xor_sync(0xFFFFFFFFu, qB, o);
        }
        if (lq == 0) {
            s_ps[half * 64 + rAl] = make_float2(sA, qA);
            s_ps[half * 64 + rBl] = make_float2(sB, qB);
        }
        __syncthreads();
        const float2 pA0 = s_ps[rAl], pA1 = s_ps[64 + rAl];
        const float2 pB0 = s_ps[rBl], pB1 = s_ps[64 + rBl];
        muA = (pA0.x + pA1.x) * (1.0f / 256.0f);
        muB = (pB0.x + pB1.x) * (1.0f / 256.0f);
        const float vA = fmaxf((pA0.y + pA1.y) * (1.0f / 256.0f) - muA * muA, 0.f);
        const float vB = fmaxf((pB0.y + pB1.y) * (1.0f / 256.0f) - muB * muB, 0.f);
        rsA = rsqrtf(vA + 1e-5f);
        rsB = rsqrtf(vB + 1e-5f);
    }

#pragma unroll
    for (int t = 0; t < 16; t++) {
        const int colt0 = ncol0 + t * 8 + lq * 2;
        float o0, o1, o2, o3;
        if (EMODE == 1) {
            const float2 gv = *(const float2*)(gamma + sc * 256 + colt0);
            const float2 ev = *(const float2*)(beta  + sc * 256 + colt0);
            o0 = fmaxf(fmaf((acc[t][0] - muA) * rsA, gv.x, ev.x), 0.f);
            o1 = fmaxf(fmaf((acc[t][1] - muA) * rsA, gv.y, ev.y), 0.f);
            o2 = fmaxf(fmaf((acc[t][2] - muB) * rsB, gv.x, ev.x), 0.f);
            o3 = fmaxf(fmaf((acc[t][3] - muB) * rsB, gv.y, ev.y), 0.f);
        } else {
            o0 = acc[t][0]; o1 = acc[t][1]; o2 = acc[t][2]; o3 = acc[t][3];
        }
        if (EMODE == 1) {
            u32* outU = (u32*)Cout;
            const int gA = hoff + rowblock + rAl;
            const int gB = hoff + rowblock + rBl;
            *(uint2*)(outU + (size_t)gA * 256 + colt0) =
                make_uint2(split_pack_val(o0), split_pack_val(o1));
            *(uint2*)(outU + (size_t)gB * 256 + colt0) =
                make_uint2(split_pack_val(o2), split_pack_val(o3));
        } else if (EMODE == 3) {
            u32* outU = (u32*)Cout;
            const uint2 pA = make_uint2(split_pack_val(o0), split_pack_val(o1));
            const uint2 pB = make_uint2(split_pack_val(o2), split_pack_val(o3));
            const int gA = rowblock + rAl, gB = rowblock + rBl;
            const int bbA = gA >> ss, jA = gA & ((1 << ss) - 1);
            const int bbB = gB >> ss, jB = gB & ((1 << ss) - 1);
            const int reps = 2048 >> ss;
            for (int rep = 0; rep < reps; rep++) {
                *(uint2*)(outU + (size_t)(bbA * 2048 + jA + (rep << ss)) * 768 + sc * 256 + colt0) = pA;
                *(uint2*)(outU + (size_t)(bbB * 2048 + jB + (rep << ss)) * 768 + sc * 256 + colt0) = pB;
            }
        } else {   // EMODE 2: f32, 4 tiled copies
            float* outF = (float*)Cout;
            const int gA = rowblock + rAl, gB = rowblock + rBl;
            const int bbA = gA >> 11, mA = gA & 2047;
            const int bbB = gB >> 11, mB = gB & 2047;
#pragma unroll
            for (int rep = 0; rep < 4; rep++) {
                *(float2*)(outF + ((size_t)bbA * 8192 + mA + rep * 2048) * 256 + colt0) =
                    make_float2(o0, o1);
                *(float2*)(outF + ((size_t)bbB * 8192 + mB + rep * 2048) * 256 + colt0) =
                    make_float2(o2, o3);
            }
        }
    }
}

// ---------------------------------------------------------------------------
extern "C" void kernel_launch(void* const* d_in, const int* in_sizes, int n_in,
                              void* d_out, int out_size)
{
    const float* features = (const float*)d_in[0];
    const float* xyz      = (const float*)d_in[1];
    const float* w1  = (const float*)d_in[2];
    const float* b1  = (const float*)d_in[3];
    const float* g1  = (const float*)d_in[4];
    const float* be1 = (const float*)d_in[5];
    const float* w2  = (const float*)d_in[6];
    const float* b2  = (const float*)d_in[7];
    const float* fw1 = (const float*)d_in[8];
    const float* fb1 = (const float*)d_in[9];
    const float* fg  = (const float*)d_in[10];
    const float* fbe = (const float*)d_in[11];
    const float* fw2 = (const float*)d_in[12];
    const float* fb2 = (const float*)d_in[13];
    float* out = (float*)d_out;

    int* idxp;   u32 *featP, *h1, *procP, *h2, *w1t, *w2t, *fw1t, *fw2t;
    cudaGetSymbolAddress((void**)&idxp, g_idx);
    cudaGetSymbolAddress((void**)&featP, g_featP);
    cudaGetSymbolAddress((void**)&h1, g_h1);
    cudaGetSymbolAddress((void**)&procP, g_procP);
    cudaGetSymbolAddress((void**)&h2, g_h2);
    cudaGetSymbolAddress((void**)&w1t, g_w1t);
    cudaGetSymbolAddress((void**)&w2t, g_w2t);
    cudaGetSymbolAddress((void**)&fw1t, g_fw1t);
    cudaGetSymbolAddress((void**)&fw2t, g_fw2t);

    cudaFuncSetAttribute(tc_gemm<0, 1>, cudaFuncAttributeMaxDynamicSharedMemorySize, TCG_SMEM);
    cudaFuncSetAttribute(tc_gemm<3, 3>, cudaFuncAttributeMaxDynamicSharedMemorySize, TCG_SMEM);
    cudaFuncSetAttribute(tc_gemm<1, 1>, cudaFuncAttributeMaxDynamicSharedMemorySize, TCG_SMEM);
    cudaFuncSetAttribute(tc_gemm<1, 2>, cudaFuncAttributeMaxDynamicSharedMemorySize, TCG_SMEM);

    // 0) FPS (exact) + conversions
    fps_kernel<<<BATCH, 1024>>>(xyz, idxp);
    split_pack<<<(BATCH * N_PTS * 256) / 256, 256>>>(features, featP, BATCH * N_PTS * 256);
    for (int sc = 0; sc < 3; sc++) {
        tsplit<<<256, 256>>>(w1 + sc * 65536, w1t + sc * 65536, 256, 256);
        tsplit<<<256, 256>>>(w2 + sc * 65536, w2t + sc * 65536, 256, 256);
    }
    tsplit<<<768, 256>>>(fw1, fw1t, 768, 256);
    tsplit<<<256, 256>>>(fw2, fw2t, 256, 256);

    // 1) Per-scale MLPs (448 x 64-row tiles over 28672 rows, scales fused)
    tc_gemm<0, 1><<<448, 256, TCG_SMEM>>>(featP, w1t, b1, g1, be1, h1, 256, idxp);
    tc_gemm<3, 3><<<448, 256, TCG_SMEM>>>(h1, w2t, b2, nullptr, nullptr, procP, 256, nullptr);

    // 2) Fusion MLP on B*2048 distinct rows; final writes 4 tiled copies.
    tc_gemm<1, 1><<<256, 256, TCG_SMEM>>>(procP, fw1t, fb1, fg, fbe, h2, 768, nullptr);
    tc_gemm<1, 2><<<256, 256, TCG_SMEM>>>(h2, fw2t, fb2, nullptr, nullptr, out, 256, nullptr);
}